// round 12
// baseline (speedup 1.0000x reference)
#include <cuda_runtime.h>
#include <cuda_bf16.h>
#include <math.h>

#define TOK 32768
#define DMODEL 256
#define HFF 1024
#define QKVD 768
#define PK 768

// ============ packed format: per (rowblk128, ktile16): 8KB block ============
// hi plane 4KB: byte = SW(row*32 + (k&15)*2); lo plane at +4096.
#define SW(b) ((b) ^ (((b) >> 3) & 0x70))

__device__ float    g_pre[TOK * DMODEL];
__device__ float    g_h0 [TOK * DMODEL];
__device__ float    g_qkv[TOK * QKVD];
__device__ float    g_h2 [TOK * DMODEL];

__device__ unsigned gp_patches[TOK * PK];   // packed, KT=48
__device__ unsigned gp_h0 [TOK * DMODEL];   // packed, KT=16
__device__ unsigned gp_hid[TOK * HFF];      // packed, KT=64
__device__ unsigned gp_tmp[TOK * DMODEL];   // packed, KT=16

// packed weights (word offsets)
#define WOFF_CONV 0
#define WOFF_QKV  196608
#define WOFF_PROJ 393216
#define WOFF_FF1  458752
#define WOFF_FF2  720896
__device__ unsigned g_wpool[983040];

// ============ helpers ============
__device__ __forceinline__ float gelu_f(float x) {
    return 0.5f * x * (1.0f + tanhf(0.7978845608028654f * (x + 0.044715f * x * x * x)));
}
__device__ __forceinline__ unsigned pack_hi(float x0, float x1, float& r0, float& r1) {
    __nv_bfloat16 h0 = __float2bfloat16_rn(x0);
    __nv_bfloat16 h1 = __float2bfloat16_rn(x1);
    r0 = x0 - __bfloat162float(h0);
    r1 = x1 - __bfloat162float(h1);
    __nv_bfloat162 hp = __halves2bfloat162(h0, h1);   // low half = even k
    return *(unsigned*)&hp;
}
__device__ __forceinline__ unsigned pack_lo(float r0, float r1) {
    __nv_bfloat162 lp = __halves2bfloat162(__float2bfloat16_rn(r0), __float2bfloat16_rn(r1));
    return *(unsigned*)&lp;
}
__device__ __forceinline__ unsigned smem_u32(const void* p) {
    unsigned a;
    asm("{ .reg .u64 t; cvta.to.shared.u64 t, %1; cvt.u32.u64 %0, t; }" : "=r"(a) : "l"(p));
    return a;
}

__device__ __forceinline__ void mma_bf16(float* d, const unsigned* a, const unsigned* b) {
    asm volatile(
        "mma.sync.aligned.m16n8k16.row.col.f32.bf16.bf16.f32 "
        "{%0,%1,%2,%3}, {%4,%5,%6,%7}, {%8,%9}, {%0,%1,%2,%3};\n"
        : "+f"(d[0]), "+f"(d[1]), "+f"(d[2]), "+f"(d[3])
        : "r"(a[0]), "r"(a[1]), "r"(a[2]), "r"(a[3]), "r"(b[0]), "r"(b[1]));
}
#define LDSM4(r0, r1, r2, r3, addr) \
    asm volatile("ldmatrix.sync.aligned.m8n8.x4.shared.b16 {%0,%1,%2,%3}, [%4];" \
                 : "=r"(r0), "=r"(r1), "=r"(r2), "=r"(r3) : "r"(addr))

// mbarrier + bulk copy
#define MBAR_INIT(addr, cnt) \
    asm volatile("mbarrier.init.shared.b64 [%0], %1;" :: "r"(addr), "r"(cnt) : "memory")
#define MBAR_EXPECT_TX(addr, bytes) \
    asm volatile("mbarrier.arrive.expect_tx.shared.b64 _, [%0], %1;" :: "r"(addr), "r"(bytes) : "memory")
#define MBAR_ARRIVE(addr) \
    asm volatile("mbarrier.arrive.shared.b64 _, [%0];" :: "r"(addr) : "memory")
#define MBAR_WAIT(addr, par) do {                                              \
    asm volatile("{\n\t.reg .pred P1;\n\t"                                     \
        "WL_%=:\n\t"                                                           \
        "mbarrier.try_wait.parity.acquire.cta.shared::cta.b64 P1, [%0], %1, 0x989680;\n\t" \
        "@P1 bra.uni WD_%=;\n\t"                                               \
        "bra.uni WL_%=;\n\t"                                                   \
        "WD_%=:\n\t}"                                                          \
        :: "r"(addr), "r"(par) : "memory");                                    \
} while (0)
#define BULK_CP(dst, src, bytes, mbar) \
    asm volatile("cp.async.bulk.shared::cluster.global.mbarrier::complete_tx::bytes [%0], [%1], %2, [%3];" \
                 :: "r"(dst), "l"(src), "r"(bytes), "r"(mbar) : "memory")

// ============ im2col -> packed patches ============
__global__ void im2col_kernel(const float* __restrict__ x) {
    int idx = blockIdx.x * blockDim.x + threadIdx.x;
    int tok = idx / 192;
    int p4  = (idx % 192) * 4;
    int b = tok >> 10;
    int n = tok & 1023;
    int ph = n >> 5, pw = n & 31;
    int c = p4 >> 8;
    int r = p4 & 255;
    int py = r >> 4, px = r & 15;
    const float* src = x + (((size_t)(b * 3 + c) * 512 + ph * 16 + py) * 512 + pw * 16 + px);
    float4 v = *(const float4*)src;
    int row = tok & 127, mb = tok >> 7;
    int kt = p4 >> 4, kloc = p4 & 15;
    unsigned w = SW((unsigned)(row * 32 + kloc * 2));
    unsigned* obk = gp_patches + ((size_t)mb * 48 + kt) * 2048 + (w >> 2);
    float r0, r1;
    unsigned h0 = pack_hi(v.x, v.y, r0, r1);
    unsigned l0 = pack_lo(r0, r1);
    unsigned h1 = pack_hi(v.z, v.w, r0, r1);
    unsigned l1 = pack_lo(r0, r1);
    *(uint2*)obk          = make_uint2(h0, h1);
    *(uint2*)(obk + 1024) = make_uint2(l0, l1);
}

// ============ LN + PE (fp32 h0 + packed h0) ============
__global__ void ln_pe_kernel(const float* __restrict__ w, const float* __restrict__ b) {
    int gt = blockIdx.x * 8 + (threadIdx.x >> 5);
    int lane = threadIdx.x & 31;
    const float4* row = (const float4*)(g_pre + (size_t)gt * DMODEL);
    float4 v0 = row[lane];
    float4 v1 = row[lane + 32];
    float s  = v0.x + v0.y + v0.z + v0.w + v1.x + v1.y + v1.z + v1.w;
    float ss = v0.x*v0.x + v0.y*v0.y + v0.z*v0.z + v0.w*v0.w
             + v1.x*v1.x + v1.y*v1.y + v1.z*v1.z + v1.w*v1.w;
    #pragma unroll
    for (int off = 16; off >= 1; off >>= 1) {
        s  += __shfl_xor_sync(0xffffffffu, s, off);
        ss += __shfl_xor_sync(0xffffffffu, ss, off);
    }
    float mean = s * (1.0f / 256.0f);
    float var  = ss * (1.0f / 256.0f) - mean * mean;
    float rstd = rsqrtf(var + 1e-5f);
    int n = gt & 1023;
    float nf = (float)n;

    float4 wv0 = ((const float4*)w)[lane];
    float4 wv1 = ((const float4*)w)[lane + 32];
    float4 bv0 = ((const float4*)b)[lane];
    float4 bv1 = ((const float4*)b)[lane + 32];

    float o[8];
    int d0 = lane * 4;
    const float C = -9.210340371976184f / 256.0f;
    float xv[8] = {v0.x, v0.y, v0.z, v0.w, v1.x, v1.y, v1.z, v1.w};
    float wv[8] = {wv0.x, wv0.y, wv0.z, wv0.w, wv1.x, wv1.y, wv1.z, wv1.w};
    float bb[8] = {bv0.x, bv0.y, bv0.z, bv0.w, bv1.x, bv1.y, bv1.z, bv1.w};
    #pragma unroll
    for (int i = 0; i < 8; i++) {
        int d = (i < 4) ? (d0 + i) : (128 + d0 + (i - 4));
        float ang = nf * expf(C * (float)(d & ~1));
        float pe = (d & 1) ? cosf(ang) : sinf(ang);
        o[i] = (xv[i] - mean) * rstd * wv[i] + bb[i] + pe;
    }
    float4* orow = (float4*)(g_h0 + (size_t)gt * DMODEL);
    orow[lane]      = make_float4(o[0], o[1], o[2], o[3]);
    orow[lane + 32] = make_float4(o[4], o[5], o[6], o[7]);

    int prow = gt & 127, mb = gt >> 7;
    #pragma unroll
    for (int half = 0; half < 2; half++) {
        int d = half * 128 + d0;
        int kt = d >> 4, kloc = d & 15;
        unsigned wsw = SW((unsigned)(prow * 32 + kloc * 2));
        unsigned* obk = gp_h0 + ((size_t)mb * 16 + kt) * 2048 + (wsw >> 2);
        float r0, r1;
        unsigned h0w = pack_hi(o[half*4+0], o[half*4+1], r0, r1);
        unsigned l0w = pack_lo(r0, r1);
        unsigned h1w = pack_hi(o[half*4+2], o[half*4+3], r0, r1);
        unsigned l1w = pack_lo(r0, r1);
        *(uint2*)obk          = make_uint2(h0w, h1w);
        *(uint2*)(obk + 1024) = make_uint2(l0w, l1w);
    }
}

// ============ weight prepack ============
__global__ void prepack_kernel(const float* __restrict__ W, unsigned* __restrict__ out,
                               int K, int KT, int total_pairs) {
    int idx = blockIdx.x * 256 + threadIdx.x;
    if (idx >= total_pairs) return;
    int kh = K >> 1;
    int nrow = idx / kh;
    int k = (idx - nrow * kh) * 2;
    int nb = nrow >> 7, row = nrow & 127;
    int kt = k >> 4, kloc = k & 15;
    float x0 = W[(size_t)nrow * K + k];
    float x1 = W[(size_t)nrow * K + k + 1];
    float r0, r1;
    unsigned hw = pack_hi(x0, x1, r0, r1);
    unsigned lw = pack_lo(r0, r1);
    unsigned wsw = SW((unsigned)(row * 32 + kloc * 2));
    unsigned* obk = out + ((size_t)nb * KT + kt) * 2048 + (wsw >> 2);
    obk[0]    = hw;
    obk[1024] = lw;
}

// ============ GEMM: mma.sync + bulk-copy pipeline ============
// CTA 128 thr (4 warps 2m x 2n), CTA tile 128x128, warp 64x64, k-tile 16,
// 5-stage pipeline, refill after mma, per-warp empty arrivals.
#define NSTAGE 5
#define STAGE_BYTES 16384
#define GEMM_SMEM_BYTES (NSTAGE * STAGE_BYTES + 1024)

template <bool GELU, bool RES, bool WF32, bool WPACK>
__global__ __launch_bounds__(128, 2)
void mp_gemm(const char* __restrict__ Ap, const char* __restrict__ Bp,
             const float* __restrict__ bias, const float* __restrict__ res,
             float* __restrict__ Cf, unsigned* __restrict__ Cp,
             int Nn, int K, int KTP) {
    extern __shared__ char dynsm[];
    __shared__ __align__(8) unsigned long long bars[2 * NSTAGE];   // full[S], empty[S]
    unsigned sbase  = (smem_u32(dynsm) + 1023u) & ~1023u;
    unsigned fullb  = smem_u32(&bars[0]);
    unsigned emptyb = smem_u32(&bars[NSTAGE]);

    int tid = threadIdx.x, warp = tid >> 5, lane = tid & 31;
    int wm = (warp >> 1) * 64, wn = (warp & 1) * 64;
    int bx = blockIdx.x, by = blockIdx.y;
    int KT = K >> 4;

    if (tid == 0) {
        #pragma unroll
        for (int s = 0; s < NSTAGE; s++) {
            MBAR_INIT(fullb + s * 8, 1);
            MBAR_INIT(emptyb + s * 8, 4);      // one arrival per warp
        }
    }
    __syncthreads();

    const char* Asrc = Ap + (size_t)by * KT * 8192;
    const char* Bsrc = Bp + (size_t)bx * KT * 8192;

    if (tid == 0) {
        #pragma unroll
        for (int s = 0; s < NSTAGE; s++) {
            MBAR_EXPECT_TX(fullb + s * 8, 16384u);
            BULK_CP(sbase + s * 16384,        Asrc + (size_t)s * 8192, 8192u, fullb + s * 8);
            BULK_CP(sbase + s * 16384 + 8192, Bsrc + (size_t)s * 8192, 8192u, fullb + s * 8);
        }
    }

    // ldmatrix lane offsets (within 4KB plane; swizzle baked since bases are 1KB-aligned)
    int arow = wm + (lane & 7) + ((lane >> 3) & 1) * 8;
    unsigned aoff[4], boff[4];
    #pragma unroll
    for (int mt = 0; mt < 4; mt++) {
        unsigned bb = (unsigned)((arow + mt * 16) * 32 + (lane >> 4) * 16);
        aoff[mt] = SW(bb);
    }
    int brow = (lane & 7) + ((lane >> 4) & 1) * 8;
    #pragma unroll
    for (int p = 0; p < 4; p++) {
        unsigned bb = (unsigned)((wn + p * 16 + brow) * 32 + ((lane >> 3) & 1) * 16);
        boff[p] = SW(bb);
    }

    float acc[4][8][4];
    #pragma unroll
    for (int i = 0; i < 4; i++)
        #pragma unroll
        for (int j = 0; j < 8; j++)
            #pragma unroll
            for (int c = 0; c < 4; c++) acc[i][j][c] = 0.0f;

    int s = 0;
    unsigned par = 0;
    for (int it = 0; it < KT; it++) {
        MBAR_WAIT(fullb + s * 8, par);
        unsigned ab = sbase + s * 16384;

        unsigned ah[4][4], al[4][4], bh[4][4], bl[4][4];
        #pragma unroll
        for (int mt = 0; mt < 4; mt++) {
            LDSM4(ah[mt][0], ah[mt][1], ah[mt][2], ah[mt][3], ab + aoff[mt]);
            LDSM4(al[mt][0], al[mt][1], al[mt][2], al[mt][3], ab + 4096 + aoff[mt]);
        }
        #pragma unroll
        for (int p = 0; p < 4; p++) {
            LDSM4(bh[p][0], bh[p][1], bh[p][2], bh[p][3], ab + 8192 + boff[p]);
            LDSM4(bl[p][0], bl[p][1], bl[p][2], bl[p][3], ab + 12288 + boff[p]);
        }
        if (lane == 0) MBAR_ARRIVE(emptyb + s * 8);   // warp-synchronous after LDSM

        #pragma unroll
        for (int mt = 0; mt < 4; mt++)
            #pragma unroll
            for (int j = 0; j < 8; j++) {
                int p = j >> 1, q = (j & 1) * 2;
                unsigned bfh[2] = {bh[p][q], bh[p][q + 1]};
                unsigned bfl[2] = {bl[p][q], bl[p][q + 1]};
                mma_bf16(acc[mt][j], ah[mt], bfh);
                mma_bf16(acc[mt][j], ah[mt], bfl);
                mma_bf16(acc[mt][j], al[mt], bfh);
            }

        // refill this stage for iteration it+NSTAGE (after mma: off the critical path)
        if (tid == 0 && it + NSTAGE < KT) {
            MBAR_WAIT(emptyb + s * 8, par);
            MBAR_EXPECT_TX(fullb + s * 8, 16384u);
            BULK_CP(ab,        Asrc + (size_t)(it + NSTAGE) * 8192, 8192u, fullb + s * 8);
            BULK_CP(ab + 8192, Bsrc + (size_t)(it + NSTAGE) * 8192, 8192u, fullb + s * 8);
        }

        if (++s == NSTAGE) { s = 0; par ^= 1; }
    }

    // epilogue
    int g = lane >> 2, t4 = lane & 3;
    #pragma unroll
    for (int mt = 0; mt < 4; mt++) {
        int lrow0 = wm + mt * 16 + g;
        #pragma unroll
        for (int j = 0; j < 8; j++) {
            int colg = bx * 128 + wn + j * 8 + t4 * 2;
            float2 b2 = *(const float2*)(bias + colg);
            #pragma unroll
            for (int h = 0; h < 2; h++) {
                int lrow = lrow0 + h * 8;
                int grow = by * 128 + lrow;
                float v0 = acc[mt][j][h * 2 + 0] + b2.x;
                float v1 = acc[mt][j][h * 2 + 1] + b2.y;
                if (GELU) { v0 = gelu_f(v0); v1 = gelu_f(v1); }
                if (RES) {
                    float2 rv = *(const float2*)(res + (size_t)grow * Nn + colg);
                    v0 += rv.x; v1 += rv.y;
                }
                if (WF32)
                    *(float2*)(Cf + (size_t)grow * Nn + colg) = make_float2(v0, v1);
                if (WPACK) {
                    int ktp = colg >> 4, kloc = colg & 15;
                    unsigned wsw = SW((unsigned)(lrow * 32 + kloc * 2));
                    unsigned* obk = Cp + ((size_t)by * KTP + ktp) * 2048 + (wsw >> 2);
                    float r0, r1;
                    unsigned hw = pack_hi(v0, v1, r0, r1);
                    obk[0]    = hw;
                    obk[1024] = pack_lo(r0, r1);
                }
            }
        }
    }
}

// ============ windowed attention (fp32 in, packed out) ============
__global__ __launch_bounds__(256)
void attn_kernel(const float* __restrict__ qkv) {
    __shared__ float Qs[64][36], Ks[64][36], Vs[64][36];
    __shared__ float Ps[64][65];
    int blk = blockIdx.x;
    int h = blk & 7, wwin = (blk >> 3) & 15, b = blk >> 7;
    int base = b * 1024 + wwin * 64;
    int t = threadIdx.x;

    for (int i = t; i < 512; i += 256) {
        int row = i >> 3, dg = (i & 7) * 4;
        const float* src = qkv + (size_t)(base + row) * QKVD + h * 32 + dg;
        *(float4*)&Qs[row][dg] = *(const float4*)(src);
        *(float4*)&Ks[row][dg] = *(const float4*)(src + 256);
        *(float4*)&Vs[row][dg] = *(const float4*)(src + 512);
    }
    __syncthreads();

    int qt  = (t >> 4) * 4;
    int kt4 = (t & 15) * 4;
    float s[4][4];
    #pragma unroll
    for (int i = 0; i < 4; i++)
        #pragma unroll
        for (int j = 0; j < 4; j++) s[i][j] = 0.0f;

    #pragma unroll
    for (int d = 0; d < 32; d += 4) {
        float4 qv[4], kv[4];
        #pragma unroll
        for (int i = 0; i < 4; i++) qv[i] = *(const float4*)&Qs[qt + i][d];
        #pragma unroll
        for (int j = 0; j < 4; j++) kv[j] = *(const float4*)&Ks[kt4 + j][d];
        #pragma unroll
        for (int i = 0; i < 4; i++)
            #pragma unroll
            for (int j = 0; j < 4; j++)
                s[i][j] += qv[i].x * kv[j].x + qv[i].y * kv[j].y +
                           qv[i].z * kv[j].z + qv[i].w * kv[j].w;
    }
    const float scale = 0.17677669529663687f;
    #pragma unroll
    for (int i = 0; i < 4; i++) {
        #pragma unroll
        for (int j = 0; j < 4; j++) s[i][j] *= scale;
        float m = fmaxf(fmaxf(s[i][0], s[i][1]), fmaxf(s[i][2], s[i][3]));
        #pragma unroll
        for (int off = 8; off >= 1; off >>= 1)
            m = fmaxf(m, __shfl_xor_sync(0xffffffffu, m, off));
        float sum = 0.0f;
        #pragma unroll
        for (int j = 0; j < 4; j++) { s[i][j] = expf(s[i][j] - m); sum += s[i][j]; }
        #pragma unroll
        for (int off = 8; off >= 1; off >>= 1)
            sum += __shfl_xor_sync(0xffffffffu, sum, off);
        float inv = 1.0f / sum;
        #pragma unroll
        for (int j = 0; j < 4; j++) Ps[qt + i][kt4 + j] = s[i][j] * inv;
    }
    __syncthreads();

    int q = t >> 2, d0 = (t & 3) * 8;
    float acc[8];
    #pragma unroll
    for (int j = 0; j < 8; j++) acc[j] = 0.0f;
    #pragma unroll 4
    for (int k = 0; k < 64; k++) {
        float p = Ps[q][k];
        float4 v0 = *(const float4*)&Vs[k][d0];
        float4 v1 = *(const float4*)&Vs[k][d0 + 4];
        acc[0] += p * v0.x; acc[1] += p * v0.y; acc[2] += p * v0.z; acc[3] += p * v0.w;
        acc[4] += p * v1.x; acc[5] += p * v1.y; acc[6] += p * v1.z; acc[7] += p * v1.w;
    }
    int tok = base + q;
    int prow = tok & 127, mb = tok >> 7;
    int col0 = h * 32 + d0;
    int kt = col0 >> 4, kloc = col0 & 15;
    unsigned wsw = SW((unsigned)(prow * 32 + kloc * 2));
    unsigned* obk = gp_tmp + ((size_t)mb * 16 + kt) * 2048 + (wsw >> 2);
    unsigned hw[4], lw[4];
    #pragma unroll
    for (int j = 0; j < 4; j++) {
        float r0, r1;
        hw[j] = pack_hi(acc[2 * j], acc[2 * j + 1], r0, r1);
        lw[j] = pack_lo(r0, r1);
    }
    *(uint4*)obk          = make_uint4(hw[0], hw[1], hw[2], hw[3]);
    *(uint4*)(obk + 1024) = make_uint4(lw[0], lw[1], lw[2], lw[3]);
}

// ============ launch ============
extern "C" void kernel_launch(void* const* d_in, const int* in_sizes, int n_in,
                              void* d_out, int out_size) {
    (void)in_sizes; (void)n_in; (void)out_size;
    const float* x      = (const float*)d_in[0];
    const float* conv_w = (const float*)d_in[1];
    const float* conv_b = (const float*)d_in[2];
    const float* ln_w   = (const float*)d_in[3];
    const float* ln_b   = (const float*)d_in[4];
    const float* qkv_w  = (const float*)d_in[5];
    const float* qkv_b  = (const float*)d_in[6];
    const float* proj_w = (const float*)d_in[7];
    const float* proj_b = (const float*)d_in[8];
    const float* ff_w1  = (const float*)d_in[9];
    const float* ff_b1  = (const float*)d_in[10];
    const float* ff_w2  = (const float*)d_in[11];
    const float* ff_b2  = (const float*)d_in[12];
    float* out = (float*)d_out;

    float *pre, *h0, *qkvf, *h2;
    unsigned *pp, *ph0, *phid, *ptmp, *wpool;
    cudaGetSymbolAddress((void**)&pre,   g_pre);
    cudaGetSymbolAddress((void**)&h0,    g_h0);
    cudaGetSymbolAddress((void**)&qkvf,  g_qkv);
    cudaGetSymbolAddress((void**)&h2,    g_h2);
    cudaGetSymbolAddress((void**)&pp,    gp_patches);
    cudaGetSymbolAddress((void**)&ph0,   gp_h0);
    cudaGetSymbolAddress((void**)&phid,  gp_hid);
    cudaGetSymbolAddress((void**)&ptmp,  gp_tmp);
    cudaGetSymbolAddress((void**)&wpool, g_wpool);

    static bool attr_done = false;
    if (!attr_done) {
        cudaFuncSetAttribute(mp_gemm<false,false,true ,false>, cudaFuncAttributeMaxDynamicSharedMemorySize, GEMM_SMEM_BYTES);
        cudaFuncSetAttribute(mp_gemm<true ,false,false,true >, cudaFuncAttributeMaxDynamicSharedMemorySize, GEMM_SMEM_BYTES);
        cudaFuncSetAttribute(mp_gemm<false,false,false,true >, cudaFuncAttributeMaxDynamicSharedMemorySize, GEMM_SMEM_BYTES);
        cudaFuncSetAttribute(mp_gemm<false,true ,true ,true >, cudaFuncAttributeMaxDynamicSharedMemorySize, GEMM_SMEM_BYTES);
        cudaFuncSetAttribute(mp_gemm<false,true ,true ,false>, cudaFuncAttributeMaxDynamicSharedMemorySize, GEMM_SMEM_BYTES);
        attr_done = true;
    }

    // 0) weight prepack (packed bf16 hi/lo blocks)
    prepack_kernel<<<(256*768/2 + 255)/256, 256>>>(conv_w, wpool + WOFF_CONV, 768, 48, 256*768/2);
    prepack_kernel<<<(768*256/2 + 255)/256, 256>>>(qkv_w,  wpool + WOFF_QKV,  256, 16, 768*256/2);
    prepack_kernel<<<(256*256/2 + 255)/256, 256>>>(proj_w, wpool + WOFF_PROJ, 256, 16, 256*256/2);
    prepack_kernel<<<(1024*256/2 + 255)/256, 256>>>(ff_w1, wpool + WOFF_FF1,  256, 16, 1024*256/2);
    prepack_kernel<<<(256*1024/2 + 255)/256, 256>>>(ff_w2, wpool + WOFF_FF2, 1024, 64, 256*1024/2);

    // 1) im2col (packed) -> embed GEMM (fp32 pre) -> LN+PE (fp32 h0 + packed)
    im2col_kernel<<<24576, 256>>>(x);
    mp_gemm<false,false,true ,false><<<dim3(2, 256), 128, GEMM_SMEM_BYTES>>>(
        (const char*)pp, (const char*)(wpool + WOFF_CONV), conv_b, nullptr, pre, nullptr, DMODEL, PK, 0);
    ln_pe_kernel<<<4096, 256>>>(ln_w, ln_b);

    // 2) FFN #1 (packed in/out)
    mp_gemm<true ,false,false,true ><<<dim3(8, 256), 128, GEMM_SMEM_BYTES>>>(
        (const char*)ph0, (const char*)(wpool + WOFF_FF1), ff_b1, nullptr, nullptr, phid, HFF, DMODEL, 64);
    mp_gemm<false,false,false,true ><<<dim3(2, 256), 128, GEMM_SMEM_BYTES>>>(
        (const char*)phid, (const char*)(wpool + WOFF_FF2), ff_b2, nullptr, nullptr, ptmp, DMODEL, HFF, 16);

    // 3) attention: qkv (fp32) -> attn (packed) -> proj (+res h0 -> fp32 h2 + packed)
    mp_gemm<false,false,true ,false><<<dim3(6, 256), 128, GEMM_SMEM_BYTES>>>(
        (const char*)ptmp, (const char*)(wpool + WOFF_QKV), qkv_b, nullptr, qkvf, nullptr, QKVD, DMODEL, 0);
    attn_kernel<<<4096, 256>>>(qkvf);
    mp_gemm<false,true ,true ,true ><<<dim3(2, 256), 128, GEMM_SMEM_BYTES>>>(
        (const char*)ptmp, (const char*)(wpool + WOFF_PROJ), proj_b, h0, h2, ph0, DMODEL, DMODEL, 16);

    // 4) FFN #2 (+res h2 -> d_out)
    mp_gemm<true ,false,false,true ><<<dim3(8, 256), 128, GEMM_SMEM_BYTES>>>(
        (const char*)ph0, (const char*)(wpool + WOFF_FF1), ff_b1, nullptr, nullptr, phid, HFF, DMODEL, 64);
    mp_gemm<false,true ,true ,false><<<dim3(2, 256), 128, GEMM_SMEM_BYTES>>>(
        (const char*)phid, (const char*)(wpool + WOFF_FF2), ff_b2, h2, out, nullptr, DMODEL, HFF, 0);
}

// round 14
// speedup vs baseline: 1.0900x; 1.0900x over previous
#include <cuda_runtime.h>
#include <cuda_bf16.h>
#include <math.h>

#define TOK 32768
#define DMODEL 256
#define HFF 1024
#define QKVD 768
#define PK 768

// ============ packed format: per (rowblk128, ktile16): 8KB block ============
// hi plane 4KB: byte = SW(row*32 + (k&15)*2); lo plane at +4096.
#define SW(b) ((b) ^ (((b) >> 3) & 0x70))

__device__ float    g_pre[TOK * DMODEL];
__device__ float    g_h0 [TOK * DMODEL];
__device__ float    g_qkv[TOK * QKVD];
__device__ float    g_h2 [TOK * DMODEL];

__device__ unsigned gp_patches[TOK * PK];   // packed, KT=48
__device__ unsigned gp_h0 [TOK * DMODEL];   // packed, KT=16
__device__ unsigned gp_hid[TOK * HFF];      // packed, KT=64
__device__ unsigned gp_tmp[TOK * DMODEL];   // packed, KT=16

// packed weights (word offsets)
#define WOFF_CONV 0
#define WOFF_QKV  196608
#define WOFF_PROJ 393216
#define WOFF_FF1  458752
#define WOFF_FF2  720896
__device__ unsigned g_wpool[983040];

// ============ helpers ============
__device__ __forceinline__ float gelu_f(float x) {
    return 0.5f * x * (1.0f + tanhf(0.7978845608028654f * (x + 0.044715f * x * x * x)));
}
__device__ __forceinline__ unsigned pack_hi(float x0, float x1, float& r0, float& r1) {
    __nv_bfloat16 h0 = __float2bfloat16_rn(x0);
    __nv_bfloat16 h1 = __float2bfloat16_rn(x1);
    r0 = x0 - __bfloat162float(h0);
    r1 = x1 - __bfloat162float(h1);
    __nv_bfloat162 hp = __halves2bfloat162(h0, h1);   // low half = even k
    return *(unsigned*)&hp;
}
__device__ __forceinline__ unsigned pack_lo(float r0, float r1) {
    __nv_bfloat162 lp = __halves2bfloat162(__float2bfloat16_rn(r0), __float2bfloat16_rn(r1));
    return *(unsigned*)&lp;
}
__device__ __forceinline__ unsigned smem_u32(const void* p) {
    unsigned a;
    asm("{ .reg .u64 t; cvta.to.shared.u64 t, %1; cvt.u32.u64 %0, t; }" : "=r"(a) : "l"(p));
    return a;
}

__device__ __forceinline__ void mma_bf16(float* d, const unsigned* a, const unsigned* b) {
    asm volatile(
        "mma.sync.aligned.m16n8k16.row.col.f32.bf16.bf16.f32 "
        "{%0,%1,%2,%3}, {%4,%5,%6,%7}, {%8,%9}, {%0,%1,%2,%3};\n"
        : "+f"(d[0]), "+f"(d[1]), "+f"(d[2]), "+f"(d[3])
        : "r"(a[0]), "r"(a[1]), "r"(a[2]), "r"(a[3]), "r"(b[0]), "r"(b[1]));
}
#define LDSM4(r0, r1, r2, r3, addr) \
    asm volatile("ldmatrix.sync.aligned.m8n8.x4.shared.b16 {%0,%1,%2,%3}, [%4];" \
                 : "=r"(r0), "=r"(r1), "=r"(r2), "=r"(r3) : "r"(addr))

// mbarrier + bulk copy
#define MBAR_INIT(addr, cnt) \
    asm volatile("mbarrier.init.shared.b64 [%0], %1;" :: "r"(addr), "r"(cnt) : "memory")
#define MBAR_EXPECT_TX(addr, bytes) \
    asm volatile("mbarrier.arrive.expect_tx.shared.b64 _, [%0], %1;" :: "r"(addr), "r"(bytes) : "memory")
#define MBAR_ARRIVE(addr) \
    asm volatile("mbarrier.arrive.shared.b64 _, [%0];" :: "r"(addr) : "memory")
#define MBAR_WAIT(addr, par) do {                                              \
    asm volatile("{\n\t.reg .pred P1;\n\t"                                     \
        "WL_%=:\n\t"                                                           \
        "mbarrier.try_wait.parity.acquire.cta.shared::cta.b64 P1, [%0], %1, 0x989680;\n\t" \
        "@P1 bra.uni WD_%=;\n\t"                                               \
        "bra.uni WL_%=;\n\t"                                                   \
        "WD_%=:\n\t}"                                                          \
        :: "r"(addr), "r"(par) : "memory");                                    \
} while (0)
#define BULK_CP(dst, src, bytes, mbar) \
    asm volatile("cp.async.bulk.shared::cluster.global.mbarrier::complete_tx::bytes [%0], [%1], %2, [%3];" \
                 :: "r"(dst), "l"(src), "r"(bytes), "r"(mbar) : "memory")

// ============ im2col -> packed patches ============
__global__ void im2col_kernel(const float* __restrict__ x) {
    int idx = blockIdx.x * blockDim.x + threadIdx.x;
    int tok = idx / 192;
    int p4  = (idx % 192) * 4;
    int b = tok >> 10;
    int n = tok & 1023;
    int ph = n >> 5, pw = n & 31;
    int c = p4 >> 8;
    int r = p4 & 255;
    int py = r >> 4, px = r & 15;
    const float* src = x + (((size_t)(b * 3 + c) * 512 + ph * 16 + py) * 512 + pw * 16 + px);
    float4 v = *(const float4*)src;
    int row = tok & 127, mb = tok >> 7;
    int kt = p4 >> 4, kloc = p4 & 15;
    unsigned w = SW((unsigned)(row * 32 + kloc * 2));
    unsigned* obk = gp_patches + ((size_t)mb * 48 + kt) * 2048 + (w >> 2);
    float r0, r1;
    unsigned h0 = pack_hi(v.x, v.y, r0, r1);
    unsigned l0 = pack_lo(r0, r1);
    unsigned h1 = pack_hi(v.z, v.w, r0, r1);
    unsigned l1 = pack_lo(r0, r1);
    *(uint2*)obk          = make_uint2(h0, h1);
    *(uint2*)(obk + 1024) = make_uint2(l0, l1);
}

// ============ LN + PE (fp32 h0 + packed h0) ============
__global__ void ln_pe_kernel(const float* __restrict__ w, const float* __restrict__ b) {
    int gt = blockIdx.x * 8 + (threadIdx.x >> 5);
    int lane = threadIdx.x & 31;
    const float4* row = (const float4*)(g_pre + (size_t)gt * DMODEL);
    float4 v0 = row[lane];
    float4 v1 = row[lane + 32];
    float s  = v0.x + v0.y + v0.z + v0.w + v1.x + v1.y + v1.z + v1.w;
    float ss = v0.x*v0.x + v0.y*v0.y + v0.z*v0.z + v0.w*v0.w
             + v1.x*v1.x + v1.y*v1.y + v1.z*v1.z + v1.w*v1.w;
    #pragma unroll
    for (int off = 16; off >= 1; off >>= 1) {
        s  += __shfl_xor_sync(0xffffffffu, s, off);
        ss += __shfl_xor_sync(0xffffffffu, ss, off);
    }
    float mean = s * (1.0f / 256.0f);
    float var  = ss * (1.0f / 256.0f) - mean * mean;
    float rstd = rsqrtf(var + 1e-5f);
    int n = gt & 1023;
    float nf = (float)n;

    float4 wv0 = ((const float4*)w)[lane];
    float4 wv1 = ((const float4*)w)[lane + 32];
    float4 bv0 = ((const float4*)b)[lane];
    float4 bv1 = ((const float4*)b)[lane + 32];

    float o[8];
    int d0 = lane * 4;
    const float C = -9.210340371976184f / 256.0f;
    float xv[8] = {v0.x, v0.y, v0.z, v0.w, v1.x, v1.y, v1.z, v1.w};
    float wv[8] = {wv0.x, wv0.y, wv0.z, wv0.w, wv1.x, wv1.y, wv1.z, wv1.w};
    float bb[8] = {bv0.x, bv0.y, bv0.z, bv0.w, bv1.x, bv1.y, bv1.z, bv1.w};
    #pragma unroll
    for (int i = 0; i < 8; i++) {
        int d = (i < 4) ? (d0 + i) : (128 + d0 + (i - 4));
        float ang = nf * expf(C * (float)(d & ~1));
        float pe = (d & 1) ? cosf(ang) : sinf(ang);
        o[i] = (xv[i] - mean) * rstd * wv[i] + bb[i] + pe;
    }
    float4* orow = (float4*)(g_h0 + (size_t)gt * DMODEL);
    orow[lane]      = make_float4(o[0], o[1], o[2], o[3]);
    orow[lane + 32] = make_float4(o[4], o[5], o[6], o[7]);

    int prow = gt & 127, mb = gt >> 7;
    #pragma unroll
    for (int half = 0; half < 2; half++) {
        int d = half * 128 + d0;
        int kt = d >> 4, kloc = d & 15;
        unsigned wsw = SW((unsigned)(prow * 32 + kloc * 2));
        unsigned* obk = gp_h0 + ((size_t)mb * 16 + kt) * 2048 + (wsw >> 2);
        float r0, r1;
        unsigned h0w = pack_hi(o[half*4+0], o[half*4+1], r0, r1);
        unsigned l0w = pack_lo(r0, r1);
        unsigned h1w = pack_hi(o[half*4+2], o[half*4+3], r0, r1);
        unsigned l1w = pack_lo(r0, r1);
        *(uint2*)obk          = make_uint2(h0w, h1w);
        *(uint2*)(obk + 1024) = make_uint2(l0w, l1w);
    }
}

// ============ weight prepack ============
__global__ void prepack_kernel(const float* __restrict__ W, unsigned* __restrict__ out,
                               int K, int KT, int total_pairs) {
    int idx = blockIdx.x * 256 + threadIdx.x;
    if (idx >= total_pairs) return;
    int kh = K >> 1;
    int nrow = idx / kh;
    int k = (idx - nrow * kh) * 2;
    int nb = nrow >> 7, row = nrow & 127;
    int kt = k >> 4, kloc = k & 15;
    float x0 = W[(size_t)nrow * K + k];
    float x1 = W[(size_t)nrow * K + k + 1];
    float r0, r1;
    unsigned hw = pack_hi(x0, x1, r0, r1);
    unsigned lw = pack_lo(r0, r1);
    unsigned wsw = SW((unsigned)(row * 32 + kloc * 2));
    unsigned* obk = out + ((size_t)nb * KT + kt) * 2048 + (wsw >> 2);
    obk[0]    = hw;
    obk[1024] = lw;
}

// ============ GEMM: mma.sync + bulk-copy pipeline ============
// CTA 256 thr (8 warps 2m x 4n), CTA tile 128x128, warp tile 64x32, k-tile 16,
// 4-stage pipeline (R11 structure), 2 CTAs/SM -> 4 warps/SMSP.
#define NSTAGE 4
#define STAGE_BYTES 16384
#define GEMM_SMEM_BYTES (NSTAGE * STAGE_BYTES + 1024)

template <bool GELU, bool RES, bool WF32, bool WPACK>
__global__ __launch_bounds__(256, 2)
void mp_gemm(const char* __restrict__ Ap, const char* __restrict__ Bp,
             const float* __restrict__ bias, const float* __restrict__ res,
             float* __restrict__ Cf, unsigned* __restrict__ Cp,
             int Nn, int K, int KTP) {
    extern __shared__ char dynsm[];
    __shared__ __align__(8) unsigned long long bars[2 * NSTAGE];   // full[S], empty[S]
    unsigned sbase  = (smem_u32(dynsm) + 1023u) & ~1023u;
    unsigned fullb  = smem_u32(&bars[0]);
    unsigned emptyb = smem_u32(&bars[NSTAGE]);

    int tid = threadIdx.x, warp = tid >> 5, lane = tid & 31;
    int wm = (warp >> 2) * 64;        // 2 m-groups
    int wn = (warp & 3) * 32;         // 4 n-groups
    int bx = blockIdx.x, by = blockIdx.y;
    int KT = K >> 4;

    if (tid == 0) {
        #pragma unroll
        for (int s = 0; s < NSTAGE; s++) {
            MBAR_INIT(fullb + s * 8, 1);
            MBAR_INIT(emptyb + s * 8, 256);    // all threads arrive
        }
    }
    __syncthreads();

    const char* Asrc = Ap + (size_t)by * KT * 8192;
    const char* Bsrc = Bp + (size_t)bx * KT * 8192;

    if (tid == 0) {
        #pragma unroll
        for (int s = 0; s < NSTAGE; s++) {
            MBAR_EXPECT_TX(fullb + s * 8, 16384u);
            BULK_CP(sbase + s * 16384,        Asrc + (size_t)s * 8192, 8192u, fullb + s * 8);
            BULK_CP(sbase + s * 16384 + 8192, Bsrc + (size_t)s * 8192, 8192u, fullb + s * 8);
        }
    }

    // ldmatrix lane offsets (within 4KB plane; swizzle baked since bases are 1KB-aligned)
    int arow = wm + (lane & 7) + ((lane >> 3) & 1) * 8;
    unsigned aoff[4], boff[2];
    #pragma unroll
    for (int mt = 0; mt < 4; mt++) {
        unsigned bb = (unsigned)((arow + mt * 16) * 32 + (lane >> 4) * 16);
        aoff[mt] = SW(bb);
    }
    int brow = (lane & 7) + ((lane >> 4) & 1) * 8;
    #pragma unroll
    for (int p = 0; p < 2; p++) {
        unsigned bb = (unsigned)((wn + p * 16 + brow) * 32 + ((lane >> 3) & 1) * 16);
        boff[p] = SW(bb);
    }

    float acc[4][4][4];
    #pragma unroll
    for (int i = 0; i < 4; i++)
        #pragma unroll
        for (int j = 0; j < 4; j++)
            #pragma unroll
            for (int c = 0; c < 4; c++) acc[i][j][c] = 0.0f;

    int s = 0;
    unsigned par = 0;
    for (int it = 0; it < KT; it++) {
        MBAR_WAIT(fullb + s * 8, par);
        unsigned ab = sbase + s * 16384;

        unsigned ah[4][4], al[4][4], bh[2][4], bl[2][4];
        #pragma unroll
        for (int mt = 0; mt < 4; mt++) {
            LDSM4(ah[mt][0], ah[mt][1], ah[mt][2], ah[mt][3], ab + aoff[mt]);
            LDSM4(al[mt][0], al[mt][1], al[mt][2], al[mt][3], ab + 4096 + aoff[mt]);
        }
        #pragma unroll
        for (int p = 0; p < 2; p++) {
            LDSM4(bh[p][0], bh[p][1], bh[p][2], bh[p][3], ab + 8192 + boff[p]);
            LDSM4(bl[p][0], bl[p][1], bl[p][2], bl[p][3], ab + 12288 + boff[p]);
        }
        MBAR_ARRIVE(emptyb + s * 8);   // all threads (R11-proven)

        // refill this stage for iteration it+NSTAGE (R11 placement)
        if (tid == 0 && it + NSTAGE < KT) {
            MBAR_WAIT(emptyb + s * 8, par);
            MBAR_EXPECT_TX(fullb + s * 8, 16384u);
            BULK_CP(ab,        Asrc + (size_t)(it + NSTAGE) * 8192, 8192u, fullb + s * 8);
            BULK_CP(ab + 8192, Bsrc + (size_t)(it + NSTAGE) * 8192, 8192u, fullb + s * 8);
        }

        #pragma unroll
        for (int mt = 0; mt < 4; mt++)
            #pragma unroll
            for (int j = 0; j < 4; j++) {
                int p = j >> 1, q = (j & 1) * 2;
                unsigned bfh[2] = {bh[p][q], bh[p][q + 1]};
                unsigned bfl[2] = {bl[p][q], bl[p][q + 1]};
                mma_bf16(acc[mt][j], ah[mt], bfh);
                mma_bf16(acc[mt][j], ah[mt], bfl);
                mma_bf16(acc[mt][j], al[mt], bfh);
            }

        if (++s == NSTAGE) { s = 0; par ^= 1; }
    }

    // epilogue
    int g = lane >> 2, t4 = lane & 3;
    #pragma unroll
    for (int mt = 0; mt < 4; mt++) {
        int lrow0 = wm + mt * 16 + g;
        #pragma unroll
        for (int j = 0; j < 4; j++) {
            int colg = bx * 128 + wn + j * 8 + t4 * 2;
            float2 b2 = *(const float2*)(bias + colg);
            #pragma unroll
            for (int h = 0; h < 2; h++) {
                int lrow = lrow0 + h * 8;
                int grow = by * 128 + lrow;
                float v0 = acc[mt][j][h * 2 + 0] + b2.x;
                float v1 = acc[mt][j][h * 2 + 1] + b2.y;
                if (GELU) { v0 = gelu_f(v0); v1 = gelu_f(v1); }
                if (RES) {
                    float2 rv = *(const float2*)(res + (size_t)grow * Nn + colg);
                    v0 += rv.x; v1 += rv.y;
                }
                if (WF32)
                    *(float2*)(Cf + (size_t)grow * Nn + colg) = make_float2(v0, v1);
                if (WPACK) {
                    int ktp = colg >> 4, kloc = colg & 15;
                    unsigned wsw = SW((unsigned)(lrow * 32 + kloc * 2));
                    unsigned* obk = Cp + ((size_t)by * KTP + ktp) * 2048 + (wsw >> 2);
                    float r0, r1;
                    unsigned hw = pack_hi(v0, v1, r0, r1);
                    obk[0]    = hw;
                    obk[1024] = pack_lo(r0, r1);
                }
            }
        }
    }
}

// ============ windowed attention (fp32 in, packed out) ============
__global__ __launch_bounds__(256)
void attn_kernel(const float* __restrict__ qkv) {
    __shared__ float Qs[64][36], Ks[64][36], Vs[64][36];
    __shared__ float Ps[64][65];
    int blk = blockIdx.x;
    int h = blk & 7, wwin = (blk >> 3) & 15, b = blk >> 7;
    int base = b * 1024 + wwin * 64;
    int t = threadIdx.x;

    for (int i = t; i < 512; i += 256) {
        int row = i >> 3, dg = (i & 7) * 4;
        const float* src = qkv + (size_t)(base + row) * QKVD + h * 32 + dg;
        *(float4*)&Qs[row][dg] = *(const float4*)(src);
        *(float4*)&Ks[row][dg] = *(const float4*)(src + 256);
        *(float4*)&Vs[row][dg] = *(const float4*)(src + 512);
    }
    __syncthreads();

    int qt  = (t >> 4) * 4;
    int kt4 = (t & 15) * 4;
    float s[4][4];
    #pragma unroll
    for (int i = 0; i < 4; i++)
        #pragma unroll
        for (int j = 0; j < 4; j++) s[i][j] = 0.0f;

    #pragma unroll
    for (int d = 0; d < 32; d += 4) {
        float4 qv[4], kv[4];
        #pragma unroll
        for (int i = 0; i < 4; i++) qv[i] = *(const float4*)&Qs[qt + i][d];
        #pragma unroll
        for (int j = 0; j < 4; j++) kv[j] = *(const float4*)&Ks[kt4 + j][d];
        #pragma unroll
        for (int i = 0; i < 4; i++)
            #pragma unroll
            for (int j = 0; j < 4; j++)
                s[i][j] += qv[i].x * kv[j].x + qv[i].y * kv[j].y +
                           qv[i].z * kv[j].z + qv[i].w * kv[j].w;
    }
    const float scale = 0.17677669529663687f;
    #pragma unroll
    for (int i = 0; i < 4; i++) {
        #pragma unroll
        for (int j = 0; j < 4; j++) s[i][j] *= scale;
        float m = fmaxf(fmaxf(s[i][0], s[i][1]), fmaxf(s[i][2], s[i][3]));
        #pragma unroll
        for (int off = 8; off >= 1; off >>= 1)
            m = fmaxf(m, __shfl_xor_sync(0xffffffffu, m, off));
        float sum = 0.0f;
        #pragma unroll
        for (int j = 0; j < 4; j++) { s[i][j] = expf(s[i][j] - m); sum += s[i][j]; }
        #pragma unroll
        for (int off = 8; off >= 1; off >>= 1)
            sum += __shfl_xor_sync(0xffffffffu, sum, off);
        float inv = 1.0f / sum;
        #pragma unroll
        for (int j = 0; j < 4; j++) Ps[qt + i][kt4 + j] = s[i][j] * inv;
    }
    __syncthreads();

    int q = t >> 2, d0 = (t & 3) * 8;
    float acc[8];
    #pragma unroll
    for (int j = 0; j < 8; j++) acc[j] = 0.0f;
    #pragma unroll 4
    for (int k = 0; k < 64; k++) {
        float p = Ps[q][k];
        float4 v0 = *(const float4*)&Vs[k][d0];
        float4 v1 = *(const float4*)&Vs[k][d0 + 4];
        acc[0] += p * v0.x; acc[1] += p * v0.y; acc[2] += p * v0.z; acc[3] += p * v0.w;
        acc[4] += p * v1.x; acc[5] += p * v1.y; acc[6] += p * v1.z; acc[7] += p * v1.w;
    }
    int tok = base + q;
    int prow = tok & 127, mb = tok >> 7;
    int col0 = h * 32 + d0;
    int kt = col0 >> 4, kloc = col0 & 15;
    unsigned wsw = SW((unsigned)(prow * 32 + kloc * 2));
    unsigned* obk = gp_tmp + ((size_t)mb * 16 + kt) * 2048 + (wsw >> 2);
    unsigned hw[4], lw[4];
    #pragma unroll
    for (int j = 0; j < 4; j++) {
        float r0, r1;
        hw[j] = pack_hi(acc[2 * j], acc[2 * j + 1], r0, r1);
        lw[j] = pack_lo(r0, r1);
    }
    *(uint4*)obk          = make_uint4(hw[0], hw[1], hw[2], hw[3]);
    *(uint4*)(obk + 1024) = make_uint4(lw[0], lw[1], lw[2], lw[3]);
}

// ============ launch ============
extern "C" void kernel_launch(void* const* d_in, const int* in_sizes, int n_in,
                              void* d_out, int out_size) {
    (void)in_sizes; (void)n_in; (void)out_size;
    const float* x      = (const float*)d_in[0];
    const float* conv_w = (const float*)d_in[1];
    const float* conv_b = (const float*)d_in[2];
    const float* ln_w   = (const float*)d_in[3];
    const float* ln_b   = (const float*)d_in[4];
    const float* qkv_w  = (const float*)d_in[5];
    const float* qkv_b  = (const float*)d_in[6];
    const float* proj_w = (const float*)d_in[7];
    const float* proj_b = (const float*)d_in[8];
    const float* ff_w1  = (const float*)d_in[9];
    const float* ff_b1  = (const float*)d_in[10];
    const float* ff_w2  = (const float*)d_in[11];
    const float* ff_b2  = (const float*)d_in[12];
    float* out = (float*)d_out;

    float *pre, *h0, *qkvf, *h2;
    unsigned *pp, *ph0, *phid, *ptmp, *wpool;
    cudaGetSymbolAddress((void**)&pre,   g_pre);
    cudaGetSymbolAddress((void**)&h0,    g_h0);
    cudaGetSymbolAddress((void**)&qkvf,  g_qkv);
    cudaGetSymbolAddress((void**)&h2,    g_h2);
    cudaGetSymbolAddress((void**)&pp,    gp_patches);
    cudaGetSymbolAddress((void**)&ph0,   gp_h0);
    cudaGetSymbolAddress((void**)&phid,  gp_hid);
    cudaGetSymbolAddress((void**)&ptmp,  gp_tmp);
    cudaGetSymbolAddress((void**)&wpool, g_wpool);

    static bool attr_done = false;
    if (!attr_done) {
        cudaFuncSetAttribute(mp_gemm<false,false,true ,false>, cudaFuncAttributeMaxDynamicSharedMemorySize, GEMM_SMEM_BYTES);
        cudaFuncSetAttribute(mp_gemm<true ,false,false,true >, cudaFuncAttributeMaxDynamicSharedMemorySize, GEMM_SMEM_BYTES);
        cudaFuncSetAttribute(mp_gemm<false,false,false,true >, cudaFuncAttributeMaxDynamicSharedMemorySize, GEMM_SMEM_BYTES);
        cudaFuncSetAttribute(mp_gemm<false,true ,true ,true >, cudaFuncAttributeMaxDynamicSharedMemorySize, GEMM_SMEM_BYTES);
        cudaFuncSetAttribute(mp_gemm<false,true ,true ,false>, cudaFuncAttributeMaxDynamicSharedMemorySize, GEMM_SMEM_BYTES);
        attr_done = true;
    }

    // 0) weight prepack (packed bf16 hi/lo blocks)
    prepack_kernel<<<(256*768/2 + 255)/256, 256>>>(conv_w, wpool + WOFF_CONV, 768, 48, 256*768/2);
    prepack_kernel<<<(768*256/2 + 255)/256, 256>>>(qkv_w,  wpool + WOFF_QKV,  256, 16, 768*256/2);
    prepack_kernel<<<(256*256/2 + 255)/256, 256>>>(proj_w, wpool + WOFF_PROJ, 256, 16, 256*256/2);
    prepack_kernel<<<(1024*256/2 + 255)/256, 256>>>(ff_w1, wpool + WOFF_FF1,  256, 16, 1024*256/2);
    prepack_kernel<<<(256*1024/2 + 255)/256, 256>>>(ff_w2, wpool + WOFF_FF2, 1024, 64, 256*1024/2);

    // 1) im2col (packed) -> embed GEMM (fp32 pre) -> LN+PE (fp32 h0 + packed)
    im2col_kernel<<<24576, 256>>>(x);
    mp_gemm<false,false,true ,false><<<dim3(2, 256), 256, GEMM_SMEM_BYTES>>>(
        (const char*)pp, (const char*)(wpool + WOFF_CONV), conv_b, nullptr, pre, nullptr, DMODEL, PK, 0);
    ln_pe_kernel<<<4096, 256>>>(ln_w, ln_b);

    // 2) FFN #1 (packed in/out)
    mp_gemm<true ,false,false,true ><<<dim3(8, 256), 256, GEMM_SMEM_BYTES>>>(
        (const char*)ph0, (const char*)(wpool + WOFF_FF1), ff_b1, nullptr, nullptr, phid, HFF, DMODEL, 64);
    mp_gemm<false,false,false,true ><<<dim3(2, 256), 256, GEMM_SMEM_BYTES>>>(
        (const char*)phid, (const char*)(wpool + WOFF_FF2), ff_b2, nullptr, nullptr, ptmp, DMODEL, HFF, 16);

    // 3) attention: qkv (fp32) -> attn (packed) -> proj (+res h0 -> fp32 h2 + packed)
    mp_gemm<false,false,true ,false><<<dim3(6, 256), 256, GEMM_SMEM_BYTES>>>(
        (const char*)ptmp, (const char*)(wpool + WOFF_QKV), qkv_b, nullptr, qkvf, nullptr, QKVD, DMODEL, 0);
    attn_kernel<<<4096, 256>>>(qkvf);
    mp_gemm<false,true ,true ,true ><<<dim3(2, 256), 256, GEMM_SMEM_BYTES>>>(
        (const char*)ptmp, (const char*)(wpool + WOFF_PROJ), proj_b, h0, h2, ph0, DMODEL, DMODEL, 16);

    // 4) FFN #2 (+res h2 -> d_out)
    mp_gemm<true ,false,false,true ><<<dim3(8, 256), 256, GEMM_SMEM_BYTES>>>(
        (const char*)ph0, (const char*)(wpool + WOFF_FF1), ff_b1, nullptr, nullptr, phid, HFF, DMODEL, 64);
    mp_gemm<false,true ,true ,false><<<dim3(2, 256), 256, GEMM_SMEM_BYTES>>>(
        (const char*)phid, (const char*)(wpool + WOFF_FF2), ff_b2, h2, out, nullptr, DMODEL, HFF, 0);
}